// round 16
// baseline (speedup 1.0000x reference)
#include <cuda_runtime.h>
#include <cuda_fp16.h>
#include <math.h>
#include <stdint.h>

// Problem constants
#define BB 4
#define SS 2048
#define DD 512
#define HH 512
#define EE 8
#define TT 8192
#define KSEL 2
#define NPAIR (TT*KSEL)
#define ECAP 8192            // per-expert bucket capacity = 2^13

// GEMM tiling (fp16)
#define BM 128
#define BN 128
#define BKH 64               // k per tile (halfs) = 128 bytes
#define NKT (512/BKH)        // 8
#define NSTG 3
#define STG_BYTES 16384u     // 128 rows x 128 B
#define SMEM_BYTES (2u*NSTG*STG_BYTES)   // 96 KB
#define NPGRID 304           // persistent grid

// combine pipeline
#define CTOK 32              // tokens per block
#define CITER 4              // iterations (8 tokens each)
#define CSTG 4               // stages
#define CSTG_BYTES 16384     // 8 tokens x 2 rows x 1024 B
#define CSMEM (CSTG*CSTG_BYTES)   // 64 KB

// ---------------- scratch ----------------
__device__ int    g_cursor[EE];
__device__ int    g_rowtok[EE*ECAP];
__device__ int    g_pos[NPAIR];
__device__ int    g_topi[NPAIR];
__device__ float  g_gatew[NPAIR];
__device__ __align__(16) __half g_xh[(size_t)TT*DD];
__device__ __align__(16) __half g_w1t[(size_t)EE*DD*HH];
__device__ __align__(16) __half g_w2t[(size_t)EE*HH*DD];
__device__ __align__(16) __half g_hh[(size_t)EE*ECAP*HH];
__device__ __align__(16) __half g_ybh[(size_t)EE*ECAP*DD];

// ---------------- helpers ----------------
__device__ __forceinline__ void cp_async16(uint32_t smem_addr, const void* gptr, int src_bytes) {
    asm volatile("cp.async.cg.shared.global [%0], [%1], 16, %2;"
                 :: "r"(smem_addr), "l"(gptr), "r"(src_bytes));
}

// ---------------- fused gating + x->half + slot assignment ----------------
__global__ void __launch_bounds__(256)
k_gate(const float* __restrict__ x, const float* __restrict__ Wg) {
    __shared__ float wgs[8 * 516];
    int tid = threadIdx.x;
    for (int d = tid; d < 512; d += 256) {
        float4 w0 = *(const float4*)(Wg + d * 8);
        float4 w1 = *(const float4*)(Wg + d * 8 + 4);
        wgs[0*516+d] = w0.x; wgs[1*516+d] = w0.y;
        wgs[2*516+d] = w0.z; wgs[3*516+d] = w0.w;
        wgs[4*516+d] = w1.x; wgs[5*516+d] = w1.y;
        wgs[6*516+d] = w1.z; wgs[7*516+d] = w1.w;
    }
    __syncthreads();

    int warp = tid >> 5, lane = tid & 31;
    int t = blockIdx.x * 8 + warp;
    const float* xr = x + (size_t)t * 512;

    {
        const float4* xv4 = (const float4*)xr;
        __half2* xh = (__half2*)(g_xh + (size_t)t * 512);
#pragma unroll
        for (int i = 0; i < 4; i++) {
            float4 v = xv4[lane + 32 * i];
            xh[(lane + 32 * i) * 2]     = __floats2half2_rn(v.x, v.y);
            xh[(lane + 32 * i) * 2 + 1] = __floats2half2_rn(v.z, v.w);
        }
    }

    int e = lane & 7, q = lane >> 3;
    const float* wrow = wgs + e * 516;
    float acc = 0.f;
#pragma unroll
    for (int i = 0; i < 32; i++) {
        int d = (q + 4 * i) * 4;
        float4 v = *(const float4*)(xr + d);
        float4 w = *(const float4*)(wrow + d);
        acc += v.x * w.x + v.y * w.y + v.z * w.z + v.w * w.w;
    }
    acc += __shfl_xor_sync(0xffffffffu, acc, 8);
    acc += __shfl_xor_sync(0xffffffffu, acc, 16);
    float lg[8];
#pragma unroll
    for (int e2 = 0; e2 < 8; e2++) lg[e2] = __shfl_sync(0xffffffffu, acc, e2);

    if (lane == 0) {
        int i0 = 0; float v0 = lg[0];
#pragma unroll
        for (int e2 = 1; e2 < 8; e2++) if (lg[e2] > v0) { v0 = lg[e2]; i0 = e2; }
        int i1 = -1; float v1 = -INFINITY;
#pragma unroll
        for (int e2 = 0; e2 < 8; e2++) if (e2 != i0 && lg[e2] > v1) { v1 = lg[e2]; i1 = e2; }
        float e1 = expf(v1 - v0);
        float w0w = 1.f / (1.f + e1);
        float w1w = e1 * w0w;
        g_topi[2*t] = i0; g_topi[2*t+1] = i1;
        g_gatew[2*t] = w0w; g_gatew[2*t+1] = w1w;
        int s0 = atomicAdd(&g_cursor[i0], 1);
        int s1 = atomicAdd(&g_cursor[i1], 1);
        g_rowtok[i0 * ECAP + s0] = t;
        g_rowtok[i1 * ECAP + s1] = t;
        g_pos[2*t]   = i0 * ECAP + s0;
        g_pos[2*t+1] = i1 * ECAP + s1;
    }
}

// ---------------- transpose + fp16 weights (one source tensor) ----------------
__global__ void k_transpose(const float* __restrict__ W, __half* __restrict__ Wout) {
    __shared__ float tile[32][33];
    int z = blockIdx.z;
    const float* src = W + (size_t)z * 262144;
    __half* dst = Wout + (size_t)z * 262144;
    int k0 = blockIdx.x * 32, n0 = blockIdx.y * 32;
    int tx = threadIdx.x, ty = threadIdx.y;
#pragma unroll
    for (int i = 0; i < 32; i += 8)
        tile[ty + i][tx] = src[(size_t)(k0 + ty + i) * 512 + n0 + tx];
    __syncthreads();
#pragma unroll
    for (int i = 0; i < 32; i += 8)
        dst[(size_t)(n0 + ty + i) * 512 + k0 + tx] = __float2half_rn(tile[tx][ty + i]);
}

// ---------------- persistent fp16 tensor-core grouped GEMM ----------------
template <int MODE>
__global__ void __launch_bounds__(256, 2)
k_gemm_h(const __half* __restrict__ Wt, const float* __restrict__ Bias) {
    extern __shared__ char smem[];
    uint32_t sbase = (uint32_t)__cvta_generic_to_shared(smem);
    uint32_t aBase = sbase;
    uint32_t bBase = sbase + NSTG * STG_BYTES;

    const int tid = threadIdx.x;
    const int lane = tid & 31, wid = tid >> 5;
    const int warp_m = wid & 3, warp_n = wid >> 2;
    const int gid = lane >> 2, tk = lane & 3;
    const int lg = lane >> 3, lr = lane & 7;
    const int chA = tid & 7;

    int total = 0;
#pragma unroll
    for (int j = 0; j < EE; j++) total += ((g_cursor[j] + 127) >> 7) * 4;

    for (int item = blockIdx.x; item < total; item += NPGRID) {
        int rem = item, e = 0, count = 0;
        while (e < EE) {
            count = g_cursor[e];
            int tiles = ((count + 127) >> 7) * 4;
            if (rem < tiles) break;
            rem -= tiles; e++;
        }
        const int m0 = (rem >> 2) * BM;
        const int n0 = (rem & 3) * BN;
        const int base = e * ECAP;
        const char* Wp = (const char*)(Wt + (size_t)e * 512 * 512);
        const float* bp = Bias + (size_t)e * 512;

        uint32_t dstOff[4];
        const char* aSrc[4]; int aOk[4];
        const char* bSrc[4];
#pragma unroll
        for (int p = 0; p < 4; p++) {
            int row = (tid >> 3) + 32 * p;
            dstOff[p] = (uint32_t)row * 128u + (uint32_t)((chA ^ (row & 7)) << 4);
            int m = m0 + row;
            if (m < count) {
                if (MODE == 0)
                    aSrc[p] = (const char*)(g_xh + (size_t)g_rowtok[base + m] * 512) + chA * 16;
                else
                    aSrc[p] = (const char*)(g_hh + (size_t)(base + m) * 512) + chA * 16;
                aOk[p] = 16;
            } else { aSrc[p] = (const char*)g_xh; aOk[p] = 0; }
            bSrc[p] = Wp + (size_t)(n0 + row) * 1024 + chA * 16;
        }

        auto issue = [&](int kt) {
            uint32_t sA = aBase + (uint32_t)(kt % NSTG) * STG_BYTES;
            uint32_t sB = bBase + (uint32_t)(kt % NSTG) * STG_BYTES;
            uint32_t koff = (uint32_t)kt * 128u;
#pragma unroll
            for (int p = 0; p < 4; p++) {
                cp_async16(sA + dstOff[p], aSrc[p] + koff, aOk[p]);
                cp_async16(sB + dstOff[p], bSrc[p] + koff, 16);
            }
            asm volatile("cp.async.commit_group;");
        };

        float acc[2][8][4];
#pragma unroll
        for (int mf = 0; mf < 2; mf++)
#pragma unroll
            for (int nf = 0; nf < 8; nf++)
#pragma unroll
                for (int q = 0; q < 4; q++) acc[mf][nf][q] = 0.f;

        issue(0); issue(1);

        for (int kt = 0; kt < NKT; kt++) {
            if (kt == NKT - 1) asm volatile("cp.async.wait_group 0;");
            else               asm volatile("cp.async.wait_group 1;");
            __syncthreads();
            if (kt + 2 < NKT) issue(kt + 2);

            uint32_t sA = aBase + (uint32_t)(kt % NSTG) * STG_BYTES;
            uint32_t sB = bBase + (uint32_t)(kt % NSTG) * STG_BYTES;

#pragma unroll
            for (int kf = 0; kf < 4; kf++) {
                uint32_t a[2][4];
#pragma unroll
                for (int mf = 0; mf < 2; mf++) {
                    int mrow = warp_m * 32 + mf * 16 + (lg & 1) * 8 + lr;
                    int ch = kf * 2 + (lg >> 1);
                    uint32_t addr = sA + (uint32_t)mrow * 128u + (uint32_t)((ch ^ (mrow & 7)) << 4);
                    asm volatile("ldmatrix.sync.aligned.m8n8.x4.shared.b16 {%0,%1,%2,%3}, [%4];"
                                 : "=r"(a[mf][0]), "=r"(a[mf][1]), "=r"(a[mf][2]), "=r"(a[mf][3])
                                 : "r"(addr));
                }
#pragma unroll
                for (int np = 0; np < 4; np++) {
                    int nrow = warp_n * 64 + np * 16 + (lg >> 1) * 8 + lr;
                    int ch = kf * 2 + (lg & 1);
                    uint32_t addr = sB + (uint32_t)nrow * 128u + (uint32_t)((ch ^ (nrow & 7)) << 4);
                    uint32_t b0v, b1v, b2v, b3v;
                    asm volatile("ldmatrix.sync.aligned.m8n8.x4.shared.b16 {%0,%1,%2,%3}, [%4];"
                                 : "=r"(b0v), "=r"(b1v), "=r"(b2v), "=r"(b3v)
                                 : "r"(addr));
#pragma unroll
                    for (int mf = 0; mf < 2; mf++) {
                        asm volatile(
                            "mma.sync.aligned.m16n8k16.row.col.f32.f16.f16.f32 "
                            "{%0,%1,%2,%3}, {%4,%5,%6,%7}, {%8,%9}, {%0,%1,%2,%3};"
                            : "+f"(acc[mf][2*np][0]), "+f"(acc[mf][2*np][1]),
                              "+f"(acc[mf][2*np][2]), "+f"(acc[mf][2*np][3])
                            : "r"(a[mf][0]), "r"(a[mf][1]), "r"(a[mf][2]), "r"(a[mf][3]),
                              "r"(b0v), "r"(b1v));
                        asm volatile(
                            "mma.sync.aligned.m16n8k16.row.col.f32.f16.f16.f32 "
                            "{%0,%1,%2,%3}, {%4,%5,%6,%7}, {%8,%9}, {%0,%1,%2,%3};"
                            : "+f"(acc[mf][2*np+1][0]), "+f"(acc[mf][2*np+1][1]),
                              "+f"(acc[mf][2*np+1][2]), "+f"(acc[mf][2*np+1][3])
                            : "r"(a[mf][0]), "r"(a[mf][1]), "r"(a[mf][2]), "r"(a[mf][3]),
                              "r"(b2v), "r"(b3v));
                    }
                }
            }
        }

        __syncthreads();   // smem reuse barrier before next item

        __half* outb = (MODE == 0) ? g_hh : g_ybh;
#pragma unroll
        for (int nf = 0; nf < 8; nf++) {
            int c = n0 + warp_n * 64 + nf * 8 + tk * 2;
            float2 bv = *(const float2*)(bp + c);
#pragma unroll
            for (int mf = 0; mf < 2; mf++) {
                int r0 = m0 + warp_m * 32 + mf * 16 + gid;
                int r1 = r0 + 8;
                if (r0 < count) {
                    float vx = acc[mf][nf][0] + bv.x;
                    float vy = acc[mf][nf][1] + bv.y;
                    if (MODE == 0) { vx = fmaxf(vx, 0.f); vy = fmaxf(vy, 0.f); }
                    *(__half2*)(outb + (size_t)(base + r0) * 512 + c) = __floats2half2_rn(vx, vy);
                }
                if (r1 < count) {
                    float vx = acc[mf][nf][2] + bv.x;
                    float vy = acc[mf][nf][3] + bv.y;
                    if (MODE == 0) { vx = fmaxf(vx, 0.f); vy = fmaxf(vy, 0.f); }
                    *(__half2*)(outb + (size_t)(base + r1) * 512 + c) = __floats2half2_rn(vx, vy);
                }
            }
        }
    }
}

// ---------------- LayerNorm + combine: cp.async staged gather ----------------
// block = 32 tokens; 4-stage pipeline of 8 tokens (16 rows, 16 KB) per stage.
__global__ void __launch_bounds__(256)
k_combine(const float* __restrict__ gamma,
          const float* __restrict__ beta,
          float* __restrict__ out) {
    extern __shared__ char csm[];
    uint32_t sb = (uint32_t)__cvta_generic_to_shared(csm);
    __shared__ int   s_slot[CTOK][2];
    __shared__ float s_w[CTOK][2];

    int tid = threadIdx.x;
    int t0 = blockIdx.x * CTOK;
    if (tid < CTOK * 2) {
        int j = tid >> 1, k = tid & 1;
        s_slot[j][k] = g_pos[2 * (t0 + j) + k];
        s_w[j][k]    = g_gatew[2 * (t0 + j) + k];
    }
    __syncthreads();

    auto issue = [&](int it) {
        uint32_t dstB = sb + (uint32_t)(it % CSTG) * CSTG_BYTES;
#pragma unroll
        for (int p = 0; p < 4; p++) {
            int c = tid + p * 256;        // 0..1023 chunk id
            int row = c >> 6;             // 0..15
            int off = (c & 63) * 16;      // byte offset within 1024B row
            int j = it * 8 + (row >> 1);
            int slot = s_slot[j][row & 1];
            const char* src = (const char*)(g_ybh + (size_t)slot * 512) + off;
            cp_async16(dstB + (uint32_t)row * 1024u + (uint32_t)off, src, 16);
        }
        asm volatile("cp.async.commit_group;");
    };

    issue(0); issue(1); issue(2);

    int warp = tid >> 5, lane = tid & 31;

    for (int it = 0; it < CITER; it++) {
        if (it < CITER - 2)      asm volatile("cp.async.wait_group 2;");
        else if (it == CITER - 2) asm volatile("cp.async.wait_group 1;");
        else                      asm volatile("cp.async.wait_group 0;");
        __syncthreads();
        if (it + 3 < CITER) issue(it + 3);

        int j = it * 8 + warp;
        int t = t0 + j;
        int slot0 = s_slot[j][0], slot1 = s_slot[j][1];
        float w0 = s_w[j][0], w1 = s_w[j][1];

        const char* stg = csm + (it % CSTG) * CSTG_BYTES + warp * 2048;
        const uint4* y0p = (const uint4*)(stg) + lane * 2;
        const uint4* y1p = (const uint4*)(stg + 1024) + lane * 2;
        uint4 ua0 = y0p[0], ua1 = y0p[1];
        uint4 ub0 = y1p[0], ub1 = y1p[1];

        float ya[16], yb[16];
        {
            const uint32_t uwa[8] = {ua0.x, ua0.y, ua0.z, ua0.w, ua1.x, ua1.y, ua1.z, ua1.w};
            const uint32_t uwb[8] = {ub0.x, ub0.y, ub0.z, ub0.w, ub1.x, ub1.y, ub1.z, ub1.w};
#pragma unroll
            for (int i = 0; i < 8; i++) {
                __half2 ha = *(const __half2*)&uwa[i];
                __half2 hb = *(const __half2*)&uwb[i];
                ya[2*i] = __low2float(ha); ya[2*i+1] = __high2float(ha);
                yb[2*i] = __low2float(hb); yb[2*i+1] = __high2float(hb);
            }
        }

        float sa = 0.f, ssa = 0.f, sbv = 0.f, ssb = 0.f;
#pragma unroll
        for (int i = 0; i < 16; i++) {
            sa += ya[i]; ssa += ya[i] * ya[i];
            sbv += yb[i]; ssb += yb[i] * yb[i];
        }
#pragma unroll
        for (int off = 16; off; off >>= 1) {
            sa  += __shfl_xor_sync(0xffffffffu, sa, off);
            ssa += __shfl_xor_sync(0xffffffffu, ssa, off);
            sbv += __shfl_xor_sync(0xffffffffu, sbv, off);
            ssb += __shfl_xor_sync(0xffffffffu, ssb, off);
        }
        float mua = sa * (1.f / 512.f);
        float wra = w0 * rsqrtf(ssa * (1.f / 512.f) - mua * mua + 1e-5f);
        float mub = sbv * (1.f / 512.f);
        float wrb = w1 * rsqrtf(ssb * (1.f / 512.f) - mub * mub + 1e-5f);

        int e0 = slot0 >> 13, e1 = slot1 >> 13;   // ECAP = 2^13
        const float4* g0 = (const float4*)(gamma + (size_t)e0 * 512) + lane * 4;
        const float4* b0 = (const float4*)(beta  + (size_t)e0 * 512) + lane * 4;
        const float4* g1 = (const float4*)(gamma + (size_t)e1 * 512) + lane * 4;
        const float4* b1 = (const float4*)(beta  + (size_t)e1 * 512) + lane * 4;

        float4* op = (float4*)(out + (size_t)t * 512) + lane * 4;
#pragma unroll
        for (int q = 0; q < 4; q++) {
            float4 g4a = g0[q], b4a = b0[q], g4b = g1[q], b4b = b1[q];
            float4 o4;
            o4.x = wra * (ya[4*q+0] - mua) * g4a.x + w0 * b4a.x
                 + wrb * (yb[4*q+0] - mub) * g4b.x + w1 * b4b.x;
            o4.y = wra * (ya[4*q+1] - mua) * g4a.y + w0 * b4a.y
                 + wrb * (yb[4*q+1] - mub) * g4b.y + w1 * b4b.y;
            o4.z = wra * (ya[4*q+2] - mua) * g4a.z + w0 * b4a.z
                 + wrb * (yb[4*q+2] - mub) * g4b.z + w1 * b4b.z;
            o4.w = wra * (ya[4*q+3] - mua) * g4a.w + w0 * b4a.w
                 + wrb * (yb[4*q+3] - mub) * g4b.w + w1 * b4b.w;
            op[q] = o4;
        }
    }
}

// ---------------- launch: two-stream overlap ----------------
extern "C" void kernel_launch(void* const* d_in, const int* in_sizes, int n_in,
                              void* d_out, int out_size) {
    const float* x     = (const float*)d_in[0];
    const float* Wg    = (const float*)d_in[1];
    const float* W1    = (const float*)d_in[2];
    const float* b1    = (const float*)d_in[3];
    const float* W2    = (const float*)d_in[4];
    const float* b2    = (const float*)d_in[5];
    const float* gamma = (const float*)d_in[6];
    const float* beta  = (const float*)d_in[7];
    float* out = (float*)d_out;

    static cudaStream_t s1 = nullptr;
    static cudaEvent_t evFork = nullptr, evGate = nullptr, evW2 = nullptr;
    static void* curAddr = nullptr;
    static int configured = 0;
    if (!configured) {
        cudaFuncSetAttribute(k_gemm_h<0>, cudaFuncAttributeMaxDynamicSharedMemorySize, SMEM_BYTES);
        cudaFuncSetAttribute(k_gemm_h<1>, cudaFuncAttributeMaxDynamicSharedMemorySize, SMEM_BYTES);
        cudaFuncSetAttribute(k_combine, cudaFuncAttributeMaxDynamicSharedMemorySize, CSMEM);
        cudaStreamCreateWithFlags(&s1, cudaStreamNonBlocking);
        cudaEventCreateWithFlags(&evFork, cudaEventDisableTiming);
        cudaEventCreateWithFlags(&evGate, cudaEventDisableTiming);
        cudaEventCreateWithFlags(&evW2, cudaEventDisableTiming);
        cudaGetSymbolAddress(&curAddr, g_cursor);
        configured = 1;
    }
    __half* w1t; cudaGetSymbolAddress((void**)&w1t, g_w1t);
    __half* w2t; cudaGetSymbolAddress((void**)&w2t, g_w2t);

    // fork
    cudaEventRecord(evFork, 0);
    cudaStreamWaitEvent(s1, evFork, 0);

    // side stream: cursors -> gate -> W2 transpose
    cudaMemsetAsync(curAddr, 0, EE * sizeof(int), s1);
    k_gate<<<TT / 8, 256, 0, s1>>>(x, Wg);
    cudaEventRecord(evGate, s1);
    k_transpose<<<dim3(16, 16, 8), dim3(32, 8), 0, s1>>>(W2, w2t);
    cudaEventRecord(evW2, s1);

    // main stream: W1 transpose -> (gate ready) -> GEMM0 -> (W2 ready) -> GEMM1 -> combine
    k_transpose<<<dim3(16, 16, 8), dim3(32, 8)>>>(W1, w1t);
    cudaStreamWaitEvent(0, evGate, 0);
    k_gemm_h<0><<<NPGRID, 256, SMEM_BYTES>>>(w1t, b1);
    cudaStreamWaitEvent(0, evW2, 0);
    k_gemm_h<1><<<NPGRID, 256, SMEM_BYTES>>>(w2t, b2);
    k_combine<<<TT / CTOK, 256, CSMEM>>>(gamma, beta, out);
}

// round 17
// speedup vs baseline: 1.0748x; 1.0748x over previous
#include <cuda_runtime.h>
#include <cuda_fp16.h>
#include <math.h>
#include <stdint.h>

// Problem constants
#define BB 4
#define SS 2048
#define DD 512
#define HH 512
#define EE 8
#define TT 8192
#define KSEL 2
#define NPAIR (TT*KSEL)
#define ECAP 8192            // per-expert bucket capacity

// GEMM tiling (fp16)
#define BM 128
#define BN 128
#define BKH 64
#define NKT (512/BKH)
#define NSTG 3
#define STG_BYTES 16384u
#define SMEM_BYTES (2u*NSTG*STG_BYTES)   // 96 KB
#define NPGRID 304

// ---------------- scratch ----------------
__device__ int    g_cursor[EE];
__device__ int    g_rowtok[EE*ECAP];
__device__ int    g_pos[NPAIR];
__device__ int    g_topi[NPAIR];
__device__ float  g_gatew[NPAIR];
__device__ __align__(16) __half g_xh[(size_t)TT*DD];
__device__ __align__(16) __half g_w1t[(size_t)EE*DD*HH];
__device__ __align__(16) __half g_w2t[(size_t)EE*HH*DD];
__device__ __align__(16) __half g_hh[(size_t)EE*ECAP*HH];
__device__ __align__(16) __half g_ybh[(size_t)EE*ECAP*DD];

// ---------------- helpers ----------------
__device__ __forceinline__ void cp_async16(uint32_t smem_addr, const void* gptr, int src_bytes) {
    asm volatile("cp.async.cg.shared.global [%0], [%1], 16, %2;"
                 :: "r"(smem_addr), "l"(gptr), "r"(src_bytes));
}

// ---------------- fused gating + x->half + slot assignment ----------------
__global__ void __launch_bounds__(256)
k_gate(const float* __restrict__ x, const float* __restrict__ Wg) {
    __shared__ float wgs[8 * 516];
    int tid = threadIdx.x;
    for (int d = tid; d < 512; d += 256) {
        float4 w0 = *(const float4*)(Wg + d * 8);
        float4 w1 = *(const float4*)(Wg + d * 8 + 4);
        wgs[0*516+d] = w0.x; wgs[1*516+d] = w0.y;
        wgs[2*516+d] = w0.z; wgs[3*516+d] = w0.w;
        wgs[4*516+d] = w1.x; wgs[5*516+d] = w1.y;
        wgs[6*516+d] = w1.z; wgs[7*516+d] = w1.w;
    }
    __syncthreads();

    int warp = tid >> 5, lane = tid & 31;
    int t = blockIdx.x * 8 + warp;
    const float* xr = x + (size_t)t * 512;

    {
        const float4* xv4 = (const float4*)xr;
        __half2* xh = (__half2*)(g_xh + (size_t)t * 512);
#pragma unroll
        for (int i = 0; i < 4; i++) {
            float4 v = xv4[lane + 32 * i];
            xh[(lane + 32 * i) * 2]     = __floats2half2_rn(v.x, v.y);
            xh[(lane + 32 * i) * 2 + 1] = __floats2half2_rn(v.z, v.w);
        }
    }

    int e = lane & 7, q = lane >> 3;
    const float* wrow = wgs + e * 516;
    float acc = 0.f;
#pragma unroll
    for (int i = 0; i < 32; i++) {
        int d = (q + 4 * i) * 4;
        float4 v = *(const float4*)(xr + d);
        float4 w = *(const float4*)(wrow + d);
        acc += v.x * w.x + v.y * w.y + v.z * w.z + v.w * w.w;
    }
    acc += __shfl_xor_sync(0xffffffffu, acc, 8);
    acc += __shfl_xor_sync(0xffffffffu, acc, 16);
    float lg[8];
#pragma unroll
    for (int e2 = 0; e2 < 8; e2++) lg[e2] = __shfl_sync(0xffffffffu, acc, e2);

    if (lane == 0) {
        int i0 = 0; float v0 = lg[0];
#pragma unroll
        for (int e2 = 1; e2 < 8; e2++) if (lg[e2] > v0) { v0 = lg[e2]; i0 = e2; }
        int i1 = -1; float v1 = -INFINITY;
#pragma unroll
        for (int e2 = 0; e2 < 8; e2++) if (e2 != i0 && lg[e2] > v1) { v1 = lg[e2]; i1 = e2; }
        float e1 = expf(v1 - v0);
        float w0w = 1.f / (1.f + e1);
        float w1w = e1 * w0w;
        g_topi[2*t] = i0; g_topi[2*t+1] = i1;
        g_gatew[2*t] = w0w; g_gatew[2*t+1] = w1w;
        int s0 = atomicAdd(&g_cursor[i0], 1);
        int s1 = atomicAdd(&g_cursor[i1], 1);
        g_rowtok[i0 * ECAP + s0] = t;
        g_rowtok[i1 * ECAP + s1] = t;
        g_pos[2*t]   = i0 * ECAP + s0;
        g_pos[2*t+1] = i1 * ECAP + s1;
    }
}

// ---------------- transpose + fp16 weights (one source tensor) ----------------
__global__ void k_transpose(const float* __restrict__ W, __half* __restrict__ Wout) {
    __shared__ float tile[32][33];
    int z = blockIdx.z;
    const float* src = W + (size_t)z * 262144;
    __half* dst = Wout + (size_t)z * 262144;
    int k0 = blockIdx.x * 32, n0 = blockIdx.y * 32;
    int tx = threadIdx.x, ty = threadIdx.y;
#pragma unroll
    for (int i = 0; i < 32; i += 8)
        tile[ty + i][tx] = src[(size_t)(k0 + ty + i) * 512 + n0 + tx];
    __syncthreads();
#pragma unroll
    for (int i = 0; i < 32; i += 8)
        dst[(size_t)(n0 + ty + i) * 512 + k0 + tx] = __float2half_rn(tile[tx][ty + i]);
}

// ---------------- persistent fp16 tensor-core grouped GEMM ----------------
template <int MODE>
__global__ void __launch_bounds__(256, 2)
k_gemm_h(const __half* __restrict__ Wt, const float* __restrict__ Bias) {
    extern __shared__ char smem[];
    uint32_t sbase = (uint32_t)__cvta_generic_to_shared(smem);
    uint32_t aBase = sbase;
    uint32_t bBase = sbase + NSTG * STG_BYTES;

    const int tid = threadIdx.x;
    const int lane = tid & 31, wid = tid >> 5;
    const int warp_m = wid & 3, warp_n = wid >> 2;
    const int gid = lane >> 2, tk = lane & 3;
    const int lg = lane >> 3, lr = lane & 7;
    const int chA = tid & 7;

    int total = 0;
#pragma unroll
    for (int j = 0; j < EE; j++) total += ((g_cursor[j] + 127) >> 7) * 4;

    for (int item = blockIdx.x; item < total; item += NPGRID) {
        int rem = item, e = 0, count = 0;
        while (e < EE) {
            count = g_cursor[e];
            int tiles = ((count + 127) >> 7) * 4;
            if (rem < tiles) break;
            rem -= tiles; e++;
        }
        const int m0 = (rem >> 2) * BM;
        const int n0 = (rem & 3) * BN;
        const int base = e * ECAP;
        const char* Wp = (const char*)(Wt + (size_t)e * 512 * 512);
        const float* bp = Bias + (size_t)e * 512;

        uint32_t dstOff[4];
        const char* aSrc[4]; int aOk[4];
        const char* bSrc[4];
#pragma unroll
        for (int p = 0; p < 4; p++) {
            int row = (tid >> 3) + 32 * p;
            dstOff[p] = (uint32_t)row * 128u + (uint32_t)((chA ^ (row & 7)) << 4);
            int m = m0 + row;
            if (m < count) {
                if (MODE == 0)
                    aSrc[p] = (const char*)(g_xh + (size_t)g_rowtok[base + m] * 512) + chA * 16;
                else
                    aSrc[p] = (const char*)(g_hh + (size_t)(base + m) * 512) + chA * 16;
                aOk[p] = 16;
            } else { aSrc[p] = (const char*)g_xh; aOk[p] = 0; }
            bSrc[p] = Wp + (size_t)(n0 + row) * 1024 + chA * 16;
        }

        auto issue = [&](int kt) {
            uint32_t sA = aBase + (uint32_t)(kt % NSTG) * STG_BYTES;
            uint32_t sB = bBase + (uint32_t)(kt % NSTG) * STG_BYTES;
            uint32_t koff = (uint32_t)kt * 128u;
#pragma unroll
            for (int p = 0; p < 4; p++) {
                cp_async16(sA + dstOff[p], aSrc[p] + koff, aOk[p]);
                cp_async16(sB + dstOff[p], bSrc[p] + koff, 16);
            }
            asm volatile("cp.async.commit_group;");
        };

        float acc[2][8][4];
#pragma unroll
        for (int mf = 0; mf < 2; mf++)
#pragma unroll
            for (int nf = 0; nf < 8; nf++)
#pragma unroll
                for (int q = 0; q < 4; q++) acc[mf][nf][q] = 0.f;

        issue(0); issue(1);

        for (int kt = 0; kt < NKT; kt++) {
            if (kt == NKT - 1) asm volatile("cp.async.wait_group 0;");
            else               asm volatile("cp.async.wait_group 1;");
            __syncthreads();
            if (kt + 2 < NKT) issue(kt + 2);

            uint32_t sA = aBase + (uint32_t)(kt % NSTG) * STG_BYTES;
            uint32_t sB = bBase + (uint32_t)(kt % NSTG) * STG_BYTES;

#pragma unroll
            for (int kf = 0; kf < 4; kf++) {
                uint32_t a[2][4];
#pragma unroll
                for (int mf = 0; mf < 2; mf++) {
                    int mrow = warp_m * 32 + mf * 16 + (lg & 1) * 8 + lr;
                    int ch = kf * 2 + (lg >> 1);
                    uint32_t addr = sA + (uint32_t)mrow * 128u + (uint32_t)((ch ^ (mrow & 7)) << 4);
                    asm volatile("ldmatrix.sync.aligned.m8n8.x4.shared.b16 {%0,%1,%2,%3}, [%4];"
                                 : "=r"(a[mf][0]), "=r"(a[mf][1]), "=r"(a[mf][2]), "=r"(a[mf][3])
                                 : "r"(addr));
                }
#pragma unroll
                for (int np = 0; np < 4; np++) {
                    int nrow = warp_n * 64 + np * 16 + (lg >> 1) * 8 + lr;
                    int ch = kf * 2 + (lg & 1);
                    uint32_t addr = sB + (uint32_t)nrow * 128u + (uint32_t)((ch ^ (nrow & 7)) << 4);
                    uint32_t b0v, b1v, b2v, b3v;
                    asm volatile("ldmatrix.sync.aligned.m8n8.x4.shared.b16 {%0,%1,%2,%3}, [%4];"
                                 : "=r"(b0v), "=r"(b1v), "=r"(b2v), "=r"(b3v)
                                 : "r"(addr));
#pragma unroll
                    for (int mf = 0; mf < 2; mf++) {
                        asm volatile(
                            "mma.sync.aligned.m16n8k16.row.col.f32.f16.f16.f32 "
                            "{%0,%1,%2,%3}, {%4,%5,%6,%7}, {%8,%9}, {%0,%1,%2,%3};"
                            : "+f"(acc[mf][2*np][0]), "+f"(acc[mf][2*np][1]),
                              "+f"(acc[mf][2*np][2]), "+f"(acc[mf][2*np][3])
                            : "r"(a[mf][0]), "r"(a[mf][1]), "r"(a[mf][2]), "r"(a[mf][3]),
                              "r"(b0v), "r"(b1v));
                        asm volatile(
                            "mma.sync.aligned.m16n8k16.row.col.f32.f16.f16.f32 "
                            "{%0,%1,%2,%3}, {%4,%5,%6,%7}, {%8,%9}, {%0,%1,%2,%3};"
                            : "+f"(acc[mf][2*np+1][0]), "+f"(acc[mf][2*np+1][1]),
                              "+f"(acc[mf][2*np+1][2]), "+f"(acc[mf][2*np+1][3])
                            : "r"(a[mf][0]), "r"(a[mf][1]), "r"(a[mf][2]), "r"(a[mf][3]),
                              "r"(b2v), "r"(b3v));
                    }
                }
            }
        }

        __syncthreads();   // smem reuse barrier before next item

        __half* outb = (MODE == 0) ? g_hh : g_ybh;
#pragma unroll
        for (int nf = 0; nf < 8; nf++) {
            int c = n0 + warp_n * 64 + nf * 8 + tk * 2;
            float2 bv = *(const float2*)(bp + c);
#pragma unroll
            for (int mf = 0; mf < 2; mf++) {
                int r0 = m0 + warp_m * 32 + mf * 16 + gid;
                int r1 = r0 + 8;
                if (r0 < count) {
                    float vx = acc[mf][nf][0] + bv.x;
                    float vy = acc[mf][nf][1] + bv.y;
                    if (MODE == 0) { vx = fmaxf(vx, 0.f); vy = fmaxf(vy, 0.f); }
                    *(__half2*)(outb + (size_t)(base + r0) * 512 + c) = __floats2half2_rn(vx, vy);
                }
                if (r1 < count) {
                    float vx = acc[mf][nf][2] + bv.x;
                    float vy = acc[mf][nf][3] + bv.y;
                    if (MODE == 0) { vx = fmaxf(vx, 0.f); vy = fmaxf(vy, 0.f); }
                    *(__half2*)(outb + (size_t)(base + r1) * 512 + c) = __floats2half2_rn(vx, vy);
                }
            }
        }
    }
}

// ---------------- LayerNorm + combine: 2 warps per token ----------------
// warp pair (2k, 2k+1) handles token; each warp owns half (256 dims) of both
// expert rows. Partial sums exchanged through smem with one block sync.
__global__ void __launch_bounds__(256)
k_combine(const float* __restrict__ gamma,
          const float* __restrict__ beta,
          float* __restrict__ out) {
    __shared__ float4 sred[8];     // per-warp partial {sa, ssa, sb, ssb}

    int tid = threadIdx.x;
    int warp = tid >> 5, lane = tid & 31;
    int t = blockIdx.x * 4 + (warp >> 1);
    int half = warp & 1;
    int ci = half * 32 + lane;     // uint4 chunk index 0..63 within the row

    int  slot0 = g_pos[2*t],   slot1 = g_pos[2*t+1];
    int  e0    = g_topi[2*t],  e1    = g_topi[2*t+1];
    float w0   = g_gatew[2*t], w1    = g_gatew[2*t+1];

    // one LDG.128 per expert per lane (both issued before any math)
    uint4 u0 = ((const uint4*)(g_ybh + (size_t)slot0 * 512))[ci];
    uint4 u1 = ((const uint4*)(g_ybh + (size_t)slot1 * 512))[ci];

    float ya[8], yb[8];
    {
        const uint32_t uwa[4] = {u0.x, u0.y, u0.z, u0.w};
        const uint32_t uwb[4] = {u1.x, u1.y, u1.z, u1.w};
#pragma unroll
        for (int i = 0; i < 4; i++) {
            __half2 ha = *(const __half2*)&uwa[i];
            __half2 hb = *(const __half2*)&uwb[i];
            ya[2*i] = __low2float(ha); ya[2*i+1] = __high2float(ha);
            yb[2*i] = __low2float(hb); yb[2*i+1] = __high2float(hb);
        }
    }

    float sa = 0.f, ssa = 0.f, sb = 0.f, ssb = 0.f;
#pragma unroll
    for (int i = 0; i < 8; i++) {
        sa += ya[i]; ssa += ya[i] * ya[i];
        sb += yb[i]; ssb += yb[i] * yb[i];
    }
#pragma unroll
    for (int off = 16; off; off >>= 1) {
        sa  += __shfl_xor_sync(0xffffffffu, sa, off);
        ssa += __shfl_xor_sync(0xffffffffu, ssa, off);
        sb  += __shfl_xor_sync(0xffffffffu, sb, off);
        ssb += __shfl_xor_sync(0xffffffffu, ssb, off);
    }
    if (lane == 0) sred[warp] = make_float4(sa, ssa, sb, ssb);
    __syncthreads();
    float4 mine = sred[warp];
    float4 peer = sred[warp ^ 1];
    sa = mine.x + peer.x; ssa = mine.y + peer.y;
    sb = mine.z + peer.z; ssb = mine.w + peer.w;

    float mua = sa * (1.f / 512.f);
    float wra = w0 * rsqrtf(ssa * (1.f / 512.f) - mua * mua + 1e-5f);
    float mub = sb * (1.f / 512.f);
    float wrb = w1 * rsqrtf(ssb * (1.f / 512.f) - mub * mub + 1e-5f);

    const float4* g0 = (const float4*)(gamma + (size_t)e0 * 512) + ci * 2;
    const float4* b0 = (const float4*)(beta  + (size_t)e0 * 512) + ci * 2;
    const float4* g1 = (const float4*)(gamma + (size_t)e1 * 512) + ci * 2;
    const float4* b1 = (const float4*)(beta  + (size_t)e1 * 512) + ci * 2;

    float4* op = (float4*)(out + (size_t)t * 512) + ci * 2;
#pragma unroll
    for (int q = 0; q < 2; q++) {
        float4 g4a = g0[q], b4a = b0[q], g4b = g1[q], b4b = b1[q];
        float4 o4;
        o4.x = wra * (ya[4*q+0] - mua) * g4a.x + w0 * b4a.x
             + wrb * (yb[4*q+0] - mub) * g4b.x + w1 * b4b.x;
        o4.y = wra * (ya[4*q+1] - mua) * g4a.y + w0 * b4a.y
             + wrb * (yb[4*q+1] - mub) * g4b.y + w1 * b4b.y;
        o4.z = wra * (ya[4*q+2] - mua) * g4a.z + w0 * b4a.z
             + wrb * (yb[4*q+2] - mub) * g4b.z + w1 * b4b.z;
        o4.w = wra * (ya[4*q+3] - mua) * g4a.w + w0 * b4a.w
             + wrb * (yb[4*q+3] - mub) * g4b.w + w1 * b4b.w;
        op[q] = o4;
    }
}

// ---------------- launch: two-stream overlap ----------------
extern "C" void kernel_launch(void* const* d_in, const int* in_sizes, int n_in,
                              void* d_out, int out_size) {
    const float* x     = (const float*)d_in[0];
    const float* Wg    = (const float*)d_in[1];
    const float* W1    = (const float*)d_in[2];
    const float* b1    = (const float*)d_in[3];
    const float* W2    = (const float*)d_in[4];
    const float* b2    = (const float*)d_in[5];
    const float* gamma = (const float*)d_in[6];
    const float* beta  = (const float*)d_in[7];
    float* out = (float*)d_out;

    static cudaStream_t s1 = nullptr;
    static cudaEvent_t evFork = nullptr, evGate = nullptr, evW2 = nullptr;
    static void* curAddr = nullptr;
    static int configured = 0;
    if (!configured) {
        cudaFuncSetAttribute(k_gemm_h<0>, cudaFuncAttributeMaxDynamicSharedMemorySize, SMEM_BYTES);
        cudaFuncSetAttribute(k_gemm_h<1>, cudaFuncAttributeMaxDynamicSharedMemorySize, SMEM_BYTES);
        cudaStreamCreateWithFlags(&s1, cudaStreamNonBlocking);
        cudaEventCreateWithFlags(&evFork, cudaEventDisableTiming);
        cudaEventCreateWithFlags(&evGate, cudaEventDisableTiming);
        cudaEventCreateWithFlags(&evW2, cudaEventDisableTiming);
        cudaGetSymbolAddress(&curAddr, g_cursor);
        configured = 1;
    }
    __half* w1t; cudaGetSymbolAddress((void**)&w1t, g_w1t);
    __half* w2t; cudaGetSymbolAddress((void**)&w2t, g_w2t);

    // fork
    cudaEventRecord(evFork, 0);
    cudaStreamWaitEvent(s1, evFork, 0);

    // side stream: cursors -> gate -> W2 transpose
    cudaMemsetAsync(curAddr, 0, EE * sizeof(int), s1);
    k_gate<<<TT / 8, 256, 0, s1>>>(x, Wg);
    cudaEventRecord(evGate, s1);
    k_transpose<<<dim3(16, 16, 8), dim3(32, 8), 0, s1>>>(W2, w2t);
    cudaEventRecord(evW2, s1);

    // main stream: W1 transpose -> (gate ready) -> GEMM0 -> (W2 ready) -> GEMM1 -> combine
    k_transpose<<<dim3(16, 16, 8), dim3(32, 8)>>>(W1, w1t);
    cudaStreamWaitEvent(0, evGate, 0);
    k_gemm_h<0><<<NPGRID, 256, SMEM_BYTES>>>(w1t, b1);
    cudaStreamWaitEvent(0, evW2, 0);
    k_gemm_h<1><<<NPGRID, 256, SMEM_BYTES>>>(w2t, b2);
    k_combine<<<TT / 4, 256>>>(gamma, beta, out);
}